// round 8
// baseline (speedup 1.0000x reference)
#include <cuda_runtime.h>
#include <cuda_bf16.h>
#include <cstdint>

// BS=64, G=64, L=100, D=64. NG=4096 groups.
// softmax shift-invariance: V_last/V_avg/b cancel => attn = softmax_l(seqs[l].(W2@p)).
// lens, W1, W3, b unused.
// FULLY FUSED: one kernel, 2048 CTAs x 256 threads, 2 groups per CTA.
// attn pooling feeds a per-CTA 2-row MLP whose weights stream through L1
// (coalesced LDG, L1-resident across waves). No intermediate global buffers.

#define NG   4096
#define L    100
#define D    64

typedef unsigned long long u64;

// ---------------------------------------------------------------------------
// f32x2 helpers
// ---------------------------------------------------------------------------
__device__ __forceinline__ u64 pk2(float v) {
    u64 r; asm("mov.b64 %0, {%1, %1};" : "=l"(r) : "f"(v)); return r;
}
__device__ __forceinline__ void fma2(u64& d, u64 a, u64 b) {
    asm("fma.rn.f32x2 %0, %1, %2, %0;" : "+l"(d) : "l"(a), "l"(b));
}
__device__ __forceinline__ void add2(u64& d, u64 a) {
    asm("add.rn.f32x2 %0, %0, %1;" : "+l"(d) : "l"(a));
}
__device__ __forceinline__ float2 unpk(u64 v) {
    float2 r; asm("mov.b64 {%0, %1}, %2;" : "=f"(r.x), "=f"(r.y) : "l"(v)); return r;
}
__device__ __forceinline__ u64 pkpair(float lo, float hi) {
    u64 r; asm("mov.b64 %0, {%1, %2};" : "=l"(r) : "f"(lo), "f"(hi)); return r;
}

// ---------------------------------------------------------------------------
// Fused kernel: attention pooling + 3-stage MLP. 2 groups/CTA, 256 threads.
// Tile in registers: slice-thread t, chunk k: row=(t>>4)+8k, cols [4*(t&15),+4).
// ---------------------------------------------------------------------------
__global__ __launch_bounds__(256) void fused_kernel(
    const float* __restrict__ seqs, const float* __restrict__ W2,
    const float* __restrict__ p,    const float* __restrict__ Wq,
    const float* __restrict__ Wl0,  const float* __restrict__ bl0,
    const float* __restrict__ Wl1,  const float* __restrict__ bl1,
    float* __restrict__ out)
{
    __shared__ float w2s[D * 65];        // stride 65: q-read conflict-free
    __shared__ float ps[D];
    __shared__ float q_s[D];
    __shared__ float attn_sh[2][104];
    __shared__ float red[2][4];
    __shared__ float part4[2][4][16][4];
    __shared__ u64 xd[2][D];             // weighted rows, duplicated {v,v}
    __shared__ u64 hdup[2][128];         // h0dup then h1dup (reused)
    __shared__ u64 h0s[2][64];           // h0 col-pairs (residual)
    __shared__ u64 parts[4][2][64];      // K-quarter partial sums

    const int tid  = threadIdx.x;
    const int half = tid >> 7;
    const int t    = tid & 127;
    const int g    = blockIdx.x * 2 + half;
    const int w    = t >> 5;
    const int lane = t & 31;
    const int c4   = t & 15;
    const int grp  = t >> 4;             // row group 0..7

    // ================= ATTENTION =================
    // ---- issue tile loads into registers (latency starts now) ----
    const float4* src = (const float4*)(seqs + (size_t)g * (L * D));
    float4 r[13];
#pragma unroll
    for (int k = 0; k < 13; ++k) {
        int idx = t + k * 128;
        if (idx < L * (D / 4)) r[k] = __ldg(src + idx);
        else                   r[k] = make_float4(0.f, 0.f, 0.f, 0.f);
    }

    // ---- coalesced stage of W2 (1024 float4) and p into shared ----
#pragma unroll
    for (int i = 0; i < 4; ++i) {
        int idx = tid + i * 256;          // < 1024
        float4 wv = __ldg((const float4*)W2 + idx);
        int row = idx >> 4, c = idx & 15;
        float* dst = &w2s[row * 65 + c * 4];
        dst[0] = wv.x; dst[1] = wv.y; dst[2] = wv.z; dst[3] = wv.w;
    }
    if (tid >= 64 && tid < 128) ps[tid - 64] = __ldg(p + tid - 64);
    __syncthreads();

    // ---- q[d] = row_d(W2) . p  (conflict-free smem) ----
    if (tid < D) {
        float acc = 0.f;
        const float* row = &w2s[tid * 65];
#pragma unroll 16
        for (int e = 0; e < D; ++e) acc += row[e] * ps[e];
        q_s[tid] = acc;
    }
    __syncthreads();

    // ---- emb: per-thread partial dot + 16-lane segmented shfl reduce ----
    const float4 q4 = *(const float4*)&q_s[c4 * 4];
#pragma unroll
    for (int k = 0; k < 13; ++k) {
        float v = r[k].x * q4.x + r[k].y * q4.y + r[k].z * q4.z + r[k].w * q4.w;
        v += __shfl_xor_sync(0xffffffffu, v, 1);
        v += __shfl_xor_sync(0xffffffffu, v, 2);
        v += __shfl_xor_sync(0xffffffffu, v, 4);
        v += __shfl_xor_sync(0xffffffffu, v, 8);
        int row = grp + 8 * k;
        if (c4 == 0 && row < L) attn_sh[half][row] = v;
    }
    __syncthreads();

    // ---- softmax over L=100 (per half: 4 warps) ----
    float v = (t < L) ? attn_sh[half][t] : -1e30f;
    float m = v;
#pragma unroll
    for (int o = 16; o > 0; o >>= 1) m = fmaxf(m, __shfl_xor_sync(0xffffffffu, m, o));
    if (lane == 0) red[half][w] = m;
    __syncthreads();
    float vmax = fmaxf(fmaxf(red[half][0], red[half][1]),
                       fmaxf(red[half][2], red[half][3]));
    __syncthreads();

    float e = (t < L) ? __expf(v - vmax) : 0.f;
    float sv = e;
#pragma unroll
    for (int o = 16; o > 0; o >>= 1) sv += __shfl_xor_sync(0xffffffffu, sv, o);
    if (lane == 0) red[half][w] = sv;
    __syncthreads();
    float inv = 1.f / (red[half][0] + red[half][1] + red[half][2] + red[half][3]);
    if (t < L) attn_sh[half][t] = e * inv;
    else if (t < 104) attn_sh[half][t] = 0.f;
    __syncthreads();

    // ---- pooling in registers ----
    float4 p4 = make_float4(0.f, 0.f, 0.f, 0.f);
#pragma unroll
    for (int k = 0; k < 13; ++k) {
        float a = attn_sh[half][grp + 8 * k];
        p4.x += a * r[k].x; p4.y += a * r[k].y;
        p4.z += a * r[k].z; p4.w += a * r[k].w;
    }
    p4.x += __shfl_xor_sync(0xffffffffu, p4.x, 16);
    p4.y += __shfl_xor_sync(0xffffffffu, p4.y, 16);
    p4.z += __shfl_xor_sync(0xffffffffu, p4.z, 16);
    p4.w += __shfl_xor_sync(0xffffffffu, p4.w, 16);
    if (lane < 16) *(float4*)&part4[half][w][lane][0] = p4;
    __syncthreads();
    if (t < D) {
        int ci = t >> 2, comp = t & 3;
        float sum = part4[half][0][ci][comp] + part4[half][1][ci][comp]
                  + part4[half][2][ci][comp] + part4[half][3][ci][comp];
        xd[half][t] = pk2(sum);          // duplicated for f32x2 MLP
    }
    __syncthreads();

    // ================= MLP (2 rows, weights via coalesced L1 LDG) =========
    // thread role: c2 = col-pair 0..63, kq = K-quarter 0..3
    const int c2 = tid & 63;
    const int kq = tid >> 6;

    // ---- stage 1: h0 = x @ Wq  (K=64, quarters of 16) ----
    {
        u64 a0 = 0ull, a1 = 0ull;
        const float* wbase = Wq + kq * 16 * 128 + 2 * c2;
#pragma unroll 16
        for (int i = 0; i < 16; ++i) {
            u64 wp = *(const u64*)(wbase + i * 128);
            int d = kq * 16 + i;
            fma2(a0, xd[0][d], wp);
            fma2(a1, xd[1][d], wp);
        }
        parts[kq][0][c2] = a0; parts[kq][1][c2] = a1;
    }
    __syncthreads();
    if (tid < 128) {
        int rr = tid >> 6, c = tid & 63;
        u64 s = parts[0][rr][c];
        add2(s, parts[1][rr][c]); add2(s, parts[2][rr][c]); add2(s, parts[3][rr][c]);
        h0s[rr][c] = s;
        float2 f = unpk(s);
        hdup[rr][2 * c]     = pk2(f.x);
        hdup[rr][2 * c + 1] = pk2(f.y);
    }
    __syncthreads();

    // ---- stage 2: h1 = relu(h0 @ Wl0 + bl0)  (K=128, quarters of 32) ----
    {
        u64 a0 = 0ull, a1 = 0ull;
        const float* wbase = Wl0 + kq * 32 * 128 + 2 * c2;
#pragma unroll 8
        for (int i = 0; i < 32; ++i) {
            u64 wp = *(const u64*)(wbase + i * 128);
            int d = kq * 32 + i;
            fma2(a0, hdup[0][d], wp);
            fma2(a1, hdup[1][d], wp);
        }
        parts[kq][0][c2] = a0; parts[kq][1][c2] = a1;
    }
    __syncthreads();
    if (tid < 128) {
        int rr = tid >> 6, c = tid & 63;
        u64 s = parts[0][rr][c];
        add2(s, parts[1][rr][c]); add2(s, parts[2][rr][c]); add2(s, parts[3][rr][c]);
        add2(s, *(const u64*)&bl0[2 * c]);
        float2 f = unpk(s);
        f.x = fmaxf(f.x, 0.f); f.y = fmaxf(f.y, 0.f);
        hdup[rr][2 * c]     = pk2(f.x);
        hdup[rr][2 * c + 1] = pk2(f.y);
    }
    __syncthreads();

    // ---- stage 3: out = h0 + relu(h1 @ Wl1 + bl1) ----
    {
        u64 a0 = 0ull, a1 = 0ull;
        const float* wbase = Wl1 + kq * 32 * 128 + 2 * c2;
#pragma unroll 8
        for (int i = 0; i < 32; ++i) {
            u64 wp = *(const u64*)(wbase + i * 128);
            int d = kq * 32 + i;
            fma2(a0, hdup[0][d], wp);
            fma2(a1, hdup[1][d], wp);
        }
        parts[kq][0][c2] = a0; parts[kq][1][c2] = a1;
    }
    __syncthreads();
    if (tid < 128) {
        int rr = tid >> 6, c = tid & 63;
        u64 s = parts[0][rr][c];
        add2(s, parts[1][rr][c]); add2(s, parts[2][rr][c]); add2(s, parts[3][rr][c]);
        add2(s, *(const u64*)&bl1[2 * c]);
        float2 f = unpk(s);
        f.x = fmaxf(f.x, 0.f); f.y = fmaxf(f.y, 0.f);
        u64 o = pkpair(f.x, f.y);
        add2(o, h0s[rr][c]);                       // residual
        int gg = blockIdx.x * 2 + rr;
        *(u64*)&out[(size_t)gg * 128 + 2 * c] = o; // STG.64, coalesced
    }
}

// ---------------------------------------------------------------------------
extern "C" void kernel_launch(void* const* d_in, const int* in_sizes, int n_in,
                              void* d_out, int out_size) {
    const float* seqs = (const float*)d_in[0];
    // d_in[1] = lens  (unused), d_in[2] = W1 (unused)
    const float* W2   = (const float*)d_in[3];
    // d_in[4] = W3 (unused), d_in[5] = b (unused)
    const float* p    = (const float*)d_in[6];
    const float* Wq   = (const float*)d_in[7];
    const float* Wl0  = (const float*)d_in[8];
    const float* bl0  = (const float*)d_in[9];
    const float* Wl1  = (const float*)d_in[10];
    const float* bl1  = (const float*)d_in[11];
    float* out = (float*)d_out;

    fused_kernel<<<NG / 2, 256>>>(seqs, W2, p, Wq, Wl0, bl0, Wl1, bl1, out);
}

// round 9
// speedup vs baseline: 1.0647x; 1.0647x over previous
#include <cuda_runtime.h>
#include <cuda_bf16.h>
#include <cstdint>

// BS=64, G=64, L=100, D=64. NG=4096 groups.
// softmax shift-invariance: V_last/V_avg/b cancel => attn = softmax_l(seqs[l].(W2@p)).
// lens, W1, W3, b unused.
// Two kernels: attn (DRAM-bound, register-tile) + MLP (smem-staged weights,
// 4x8 f32x2 register tiles, 2-way K-split, 256 threads).

#define NG   4096
#define L    100
#define D    64

typedef unsigned long long u64;

__device__ float g_weighted[NG * D];     // attention-pooled rows

// ---------------------------------------------------------------------------
// helpers
// ---------------------------------------------------------------------------
__device__ __forceinline__ void cp16(unsigned int s_addr, const void* g) {
    asm volatile("cp.async.cg.shared.global [%0], [%1], 16;\n" :: "r"(s_addr), "l"(g));
}
#define CP_COMMIT() asm volatile("cp.async.commit_group;\n" ::: "memory")
#define CP_WAIT(n)  asm volatile("cp.async.wait_group %0;\n" :: "n"(n) : "memory")

__device__ __forceinline__ u64 pk2(float v) {
    u64 r; asm("mov.b64 %0, {%1, %1};" : "=l"(r) : "f"(v)); return r;
}
__device__ __forceinline__ void fma2(u64& d, u64 a, u64 b) {
    asm("fma.rn.f32x2 %0, %1, %2, %0;" : "+l"(d) : "l"(a), "l"(b));
}
__device__ __forceinline__ void add2(u64& d, u64 a) {
    asm("add.rn.f32x2 %0, %0, %1;" : "+l"(d) : "l"(a));
}
__device__ __forceinline__ float2 unpk(u64 v) {
    float2 r; asm("mov.b64 {%0, %1}, %2;" : "=f"(r.x), "=f"(r.y) : "l"(v)); return r;
}
__device__ __forceinline__ u64 pkpair(float lo, float hi) {
    u64 r; asm("mov.b64 %0, {%1, %2};" : "=l"(r) : "f"(lo), "f"(hi)); return r;
}

// ---------------------------------------------------------------------------
// Kernel 1: attention pooling, 2 groups per block, 256 threads. (R6, unchanged)
// ---------------------------------------------------------------------------
__global__ __launch_bounds__(256) void attn_kernel(
    const float* __restrict__ seqs, const float* __restrict__ W2,
    const float* __restrict__ p)
{
    __shared__ float w2s[D * 65];
    __shared__ float ps[D];
    __shared__ float q_s[D];
    __shared__ float attn_sh[2][104];
    __shared__ float red[2][4];
    __shared__ float part4[2][4][16][4];

    const int tid  = threadIdx.x;
    const int half = tid >> 7;
    const int t    = tid & 127;
    const int g    = blockIdx.x * 2 + half;
    const int w    = t >> 5;
    const int lane = t & 31;
    const int c4   = t & 15;
    const int grp  = t >> 4;

    const float4* src = (const float4*)(seqs + (size_t)g * (L * D));
    float4 r[13];
#pragma unroll
    for (int k = 0; k < 13; ++k) {
        int idx = t + k * 128;
        if (idx < L * (D / 4)) r[k] = __ldg(src + idx);
        else                   r[k] = make_float4(0.f, 0.f, 0.f, 0.f);
    }

#pragma unroll
    for (int i = 0; i < 4; ++i) {
        int idx = tid + i * 256;
        float4 wv = __ldg((const float4*)W2 + idx);
        int row = idx >> 4, c = idx & 15;
        float* dst = &w2s[row * 65 + c * 4];
        dst[0] = wv.x; dst[1] = wv.y; dst[2] = wv.z; dst[3] = wv.w;
    }
    if (tid >= 64 && tid < 128) ps[tid - 64] = __ldg(p + tid - 64);
    __syncthreads();

    if (tid < D) {
        float acc = 0.f;
        const float* row = &w2s[tid * 65];
#pragma unroll 16
        for (int e = 0; e < D; ++e) acc += row[e] * ps[e];
        q_s[tid] = acc;
    }
    __syncthreads();

    const float4 q4 = *(const float4*)&q_s[c4 * 4];
#pragma unroll
    for (int k = 0; k < 13; ++k) {
        float v = r[k].x * q4.x + r[k].y * q4.y + r[k].z * q4.z + r[k].w * q4.w;
        v += __shfl_xor_sync(0xffffffffu, v, 1);
        v += __shfl_xor_sync(0xffffffffu, v, 2);
        v += __shfl_xor_sync(0xffffffffu, v, 4);
        v += __shfl_xor_sync(0xffffffffu, v, 8);
        int row = grp + 8 * k;
        if (c4 == 0 && row < L) attn_sh[half][row] = v;
    }
    __syncthreads();

    float v = (t < L) ? attn_sh[half][t] : -1e30f;
    float m = v;
#pragma unroll
    for (int o = 16; o > 0; o >>= 1) m = fmaxf(m, __shfl_xor_sync(0xffffffffu, m, o));
    if (lane == 0) red[half][w] = m;
    __syncthreads();
    float vmax = fmaxf(fmaxf(red[half][0], red[half][1]),
                       fmaxf(red[half][2], red[half][3]));
    __syncthreads();

    float e = (t < L) ? __expf(v - vmax) : 0.f;
    float sv = e;
#pragma unroll
    for (int o = 16; o > 0; o >>= 1) sv += __shfl_xor_sync(0xffffffffu, sv, o);
    if (lane == 0) red[half][w] = sv;
    __syncthreads();
    float inv = 1.f / (red[half][0] + red[half][1] + red[half][2] + red[half][3]);
    if (t < L) attn_sh[half][t] = e * inv;
    else if (t < 104) attn_sh[half][t] = 0.f;
    __syncthreads();

    float4 p4 = make_float4(0.f, 0.f, 0.f, 0.f);
#pragma unroll
    for (int k = 0; k < 13; ++k) {
        float a = attn_sh[half][grp + 8 * k];
        p4.x += a * r[k].x; p4.y += a * r[k].y;
        p4.z += a * r[k].z; p4.w += a * r[k].w;
    }
    p4.x += __shfl_xor_sync(0xffffffffu, p4.x, 16);
    p4.y += __shfl_xor_sync(0xffffffffu, p4.y, 16);
    p4.z += __shfl_xor_sync(0xffffffffu, p4.z, 16);
    p4.w += __shfl_xor_sync(0xffffffffu, p4.w, 16);
    if (lane < 16) *(float4*)&part4[half][w][lane][0] = p4;
    __syncthreads();
    if (t < D) {
        int ci = t >> 2, comp = t & 3;
        float sum = part4[half][0][ci][comp] + part4[half][1][ci][comp]
                  + part4[half][2][ci][comp] + part4[half][3][ci][comp];
        g_weighted[g * D + t] = sum;
    }
}

// ---------------------------------------------------------------------------
// MLP: 128 blocks x 256 threads, 32 rows/block.
// Thread = (ct 0..15 cols[8ct,+8), rt 0..7 rows[4rt,+4), kh 0..1 K-half).
// 16 f32x2 accumulators/thread; stage inputs pre-duplicated u64 in smem.
// parts buffer aliases the stage-1 sx input (sync-protected).
// ---------------------------------------------------------------------------
template<int K, bool DUPIN, bool BIAS, bool RELU, bool STOREH0, bool FINAL>
__device__ __forceinline__ void mlp_stage(
    const float* __restrict__ ws,       // weights [K][128] smem
    const float* __restrict__ sxf,      // plain-float input (DUPIN=false)
    const u64*   __restrict__ hin,      // duplicated input  (DUPIN=true)
    u64* __restrict__ parts,            // [32][64] u64 (aliases sx)
    u64* __restrict__ h0res,            // [32][64] u64
    u64* __restrict__ hout,             // [32][128] u64 duplicated
    const float* __restrict__ bias,
    float* __restrict__ gout, int grow0,
    int kh, int r0, int c0)
{
    u64 acc[4][4];
#pragma unroll
    for (int i = 0; i < 4; ++i)
#pragma unroll
        for (int j = 0; j < 4; ++j) acc[i][j] = 0ull;

    const int dbase = kh * (K / 2);
#pragma unroll 4
    for (int i = 0; i < K / 2; ++i) {
        const int dd = dbase + i;
        const u64* wp = (const u64*)&ws[dd * 128 + c0];
        u64 b0 = wp[0], b1 = wp[1], b2 = wp[2], b3 = wp[3];
#pragma unroll
        for (int row = 0; row < 4; ++row) {
            u64 x;
            if (DUPIN) x = hin[(r0 + row) * 128 + dd];
            else       x = pk2(sxf[(r0 + row) * 64 + dd]);
            fma2(acc[row][0], x, b0);
            fma2(acc[row][1], x, b1);
            fma2(acc[row][2], x, b2);
            fma2(acc[row][3], x, b3);
        }
    }
    __syncthreads();                     // all reads of input (and sx alias) done

    if (kh) {
#pragma unroll
        for (int row = 0; row < 4; ++row)
#pragma unroll
            for (int j = 0; j < 4; ++j)
                parts[(r0 + row) * 64 + (c0 >> 1) + j] = acc[row][j];
    }
    __syncthreads();

    if (!kh) {
        u64 bv[4];
        if (BIAS) {
#pragma unroll
            for (int j = 0; j < 4; ++j) bv[j] = *(const u64*)&bias[c0 + 2 * j];
        }
#pragma unroll
        for (int row = 0; row < 4; ++row) {
#pragma unroll
            for (int j = 0; j < 4; ++j) {
                u64 s = acc[row][j];
                add2(s, parts[(r0 + row) * 64 + (c0 >> 1) + j]);
                if (BIAS) add2(s, bv[j]);
                float2 f = unpk(s);
                if (RELU) { f.x = fmaxf(f.x, 0.f); f.y = fmaxf(f.y, 0.f); }
                if (STOREH0)
                    h0res[(r0 + row) * 64 + (c0 >> 1) + j] = s;
                if (FINAL) {
                    u64 o = pkpair(f.x, f.y);
                    add2(o, h0res[(r0 + row) * 64 + (c0 >> 1) + j]);
                    *(u64*)&gout[(size_t)(grow0 + r0 + row) * 128 + c0 + 2 * j] = o;
                } else {
                    hout[(r0 + row) * 128 + c0 + 2 * j]     = pk2(f.x);
                    hout[(r0 + row) * 128 + c0 + 2 * j + 1] = pk2(f.y);
                }
            }
        }
    }
    __syncthreads();
}

__global__ __launch_bounds__(256) void mlp_kernel(
    const float* __restrict__ Wq,  const float* __restrict__ Wl0,
    const float* __restrict__ bl0, const float* __restrict__ Wl1,
    const float* __restrict__ bl1, float* __restrict__ out)
{
    extern __shared__ float smem[];
    float* regA  = smem;            // 4096 f: sx [32][64] then parts u64[32][64]
    float* h0res = smem + 4096;     // 4096 f: u64[32][64]
    float* hdup  = smem + 8192;     // 8192 f: u64[32][128]
    float* wq    = smem + 16384;    // 8192 f
    float* wl0   = smem + 24576;    // 16384 f
    float* wl1   = smem + 40960;    // 16384 f   (total 57344 f = 224 KB)

    const int t    = threadIdx.x;
    const int row0 = blockIdx.x * 32;
    const unsigned int sb = (unsigned int)__cvta_generic_to_shared(smem);

    // ---- async staging: G0 = sx + Wq, G1 = Wl0, G2 = Wl1 ----
    {
        const float4* xs = (const float4*)(g_weighted + (size_t)row0 * D);
#pragma unroll
        for (int i = 0; i < 2; ++i) {
            int idx = t + i * 256;                             // 512 f4
            cp16(sb + (0 + idx * 4) * 4, xs + idx);
        }
#pragma unroll
        for (int i = 0; i < 8; ++i) {
            int idx = t + i * 256;                             // 2048 f4
            cp16(sb + (16384 + idx * 4) * 4, (const float4*)Wq + idx);
        }
        CP_COMMIT();
#pragma unroll
        for (int i = 0; i < 16; ++i) {
            int idx = t + i * 256;                             // 4096 f4
            cp16(sb + (24576 + idx * 4) * 4, (const float4*)Wl0 + idx);
        }
        CP_COMMIT();
#pragma unroll
        for (int i = 0; i < 16; ++i) {
            int idx = t + i * 256;
            cp16(sb + (40960 + idx * 4) * 4, (const float4*)Wl1 + idx);
        }
        CP_COMMIT();
    }

    const int ct = t & 15;          // col tile -> cols [8ct, 8ct+8)
    const int rt = (t >> 4) & 7;    // row tile -> rows [4rt, 4rt+4)
    const int kh = t >> 7;          // K-half
    const int r0 = rt * 4, c0 = ct * 8;

    u64* parts = (u64*)regA;
    u64* h0r   = (u64*)h0res;
    u64* hd    = (u64*)hdup;

    // ---- stage 1: h0 = X @ Wq (K=64); store h0res + hdup ----
    CP_WAIT(2);
    __syncthreads();
    mlp_stage<64, false, false, false, true, false>(
        wq, regA, nullptr, parts, h0r, hd, nullptr, nullptr, 0, kh, r0, c0);

    // ---- stage 2: h1 = relu(h0 @ Wl0 + bl0); overwrite hdup ----
    CP_WAIT(1);
    __syncthreads();
    mlp_stage<128, true, true, true, false, false>(
        wl0, nullptr, hd, parts, h0r, hd, bl0, nullptr, 0, kh, r0, c0);

    // ---- stage 3: out = h0 + relu(h1 @ Wl1 + bl1) ----
    CP_WAIT(0);
    __syncthreads();
    mlp_stage<128, true, true, true, false, true>(
        wl1, nullptr, hd, parts, h0r, hd, bl1, out, row0, kh, r0, c0);
}

// ---------------------------------------------------------------------------
extern "C" void kernel_launch(void* const* d_in, const int* in_sizes, int n_in,
                              void* d_out, int out_size) {
    const float* seqs = (const float*)d_in[0];
    const float* W2   = (const float*)d_in[3];
    const float* p    = (const float*)d_in[6];
    const float* Wq   = (const float*)d_in[7];
    const float* Wl0  = (const float*)d_in[8];
    const float* bl0  = (const float*)d_in[9];
    const float* Wl1  = (const float*)d_in[10];
    const float* bl1  = (const float*)d_in[11];
    float* out = (float*)d_out;

    static bool init_done = false;
    if (!init_done) {
        cudaFuncSetAttribute(mlp_kernel,
                             cudaFuncAttributeMaxDynamicSharedMemorySize, 229376);
        init_done = true;
    }

    attn_kernel<<<NG / 2, 256>>>(seqs, W2, p);
    mlp_kernel<<<NG / 32, 256, 229376>>>(Wq, Wl0, bl0, Wl1, bl1, out);
}

// round 10
// speedup vs baseline: 1.2971x; 1.2183x over previous
#include <cuda_runtime.h>
#include <cuda_bf16.h>
#include <cstdint>

// BS=64, G=64, L=100, D=64. NG=4096 groups.
// softmax shift-invariance: V_last/V_avg/b cancel => attn = softmax_l(seqs[l].(W2@p)).
// lens, W1, W3, b unused.
// attn: R6 version (20.6us, DRAM-bound). MLP: R6 structure + 4d-batched
// inner loop with hoisted independent LDS.128s for ILP.

#define NG   4096
#define L    100
#define D    64

typedef unsigned long long u64;

__device__ float g_weighted[NG * D];     // attention-pooled rows

// ---------------------------------------------------------------------------
// helpers
// ---------------------------------------------------------------------------
__device__ __forceinline__ void cp16(unsigned int s_addr, const void* g) {
    asm volatile("cp.async.cg.shared.global [%0], [%1], 16;\n" :: "r"(s_addr), "l"(g));
}
#define CP_COMMIT() asm volatile("cp.async.commit_group;\n" ::: "memory")
#define CP_WAIT(n)  asm volatile("cp.async.wait_group %0;\n" :: "n"(n) : "memory")

__device__ __forceinline__ u64 pk2(float v) {
    u64 r; asm("mov.b64 %0, {%1, %1};" : "=l"(r) : "f"(v)); return r;
}
__device__ __forceinline__ void fma2(u64& d, u64 a, u64 b) {
    asm("fma.rn.f32x2 %0, %1, %2, %0;" : "+l"(d) : "l"(a), "l"(b));
}
__device__ __forceinline__ float2 unpk(u64 v) {
    float2 r; asm("mov.b64 {%0, %1}, %2;" : "=f"(r.x), "=f"(r.y) : "l"(v)); return r;
}

// ---------------------------------------------------------------------------
// Kernel 1: attention pooling, 2 groups per block, 256 threads. (R6, unchanged)
// ---------------------------------------------------------------------------
__global__ __launch_bounds__(256) void attn_kernel(
    const float* __restrict__ seqs, const float* __restrict__ W2,
    const float* __restrict__ p)
{
    __shared__ float w2s[D * 65];
    __shared__ float ps[D];
    __shared__ float q_s[D];
    __shared__ float attn_sh[2][104];
    __shared__ float red[2][4];
    __shared__ float part4[2][4][16][4];

    const int tid  = threadIdx.x;
    const int half = tid >> 7;
    const int t    = tid & 127;
    const int g    = blockIdx.x * 2 + half;
    const int w    = t >> 5;
    const int lane = t & 31;
    const int c4   = t & 15;
    const int grp  = t >> 4;

    const float4* src = (const float4*)(seqs + (size_t)g * (L * D));
    float4 r[13];
#pragma unroll
    for (int k = 0; k < 13; ++k) {
        int idx = t + k * 128;
        if (idx < L * (D / 4)) r[k] = __ldg(src + idx);
        else                   r[k] = make_float4(0.f, 0.f, 0.f, 0.f);
    }

#pragma unroll
    for (int i = 0; i < 4; ++i) {
        int idx = tid + i * 256;
        float4 wv = __ldg((const float4*)W2 + idx);
        int row = idx >> 4, c = idx & 15;
        float* dst = &w2s[row * 65 + c * 4];
        dst[0] = wv.x; dst[1] = wv.y; dst[2] = wv.z; dst[3] = wv.w;
    }
    if (tid >= 64 && tid < 128) ps[tid - 64] = __ldg(p + tid - 64);
    __syncthreads();

    if (tid < D) {
        float acc = 0.f;
        const float* row = &w2s[tid * 65];
#pragma unroll 16
        for (int e = 0; e < D; ++e) acc += row[e] * ps[e];
        q_s[tid] = acc;
    }
    __syncthreads();

    const float4 q4 = *(const float4*)&q_s[c4 * 4];
#pragma unroll
    for (int k = 0; k < 13; ++k) {
        float v = r[k].x * q4.x + r[k].y * q4.y + r[k].z * q4.z + r[k].w * q4.w;
        v += __shfl_xor_sync(0xffffffffu, v, 1);
        v += __shfl_xor_sync(0xffffffffu, v, 2);
        v += __shfl_xor_sync(0xffffffffu, v, 4);
        v += __shfl_xor_sync(0xffffffffu, v, 8);
        int row = grp + 8 * k;
        if (c4 == 0 && row < L) attn_sh[half][row] = v;
    }
    __syncthreads();

    float v = (t < L) ? attn_sh[half][t] : -1e30f;
    float m = v;
#pragma unroll
    for (int o = 16; o > 0; o >>= 1) m = fmaxf(m, __shfl_xor_sync(0xffffffffu, m, o));
    if (lane == 0) red[half][w] = m;
    __syncthreads();
    float vmax = fmaxf(fmaxf(red[half][0], red[half][1]),
                       fmaxf(red[half][2], red[half][3]));
    __syncthreads();

    float e = (t < L) ? __expf(v - vmax) : 0.f;
    float sv = e;
#pragma unroll
    for (int o = 16; o > 0; o >>= 1) sv += __shfl_xor_sync(0xffffffffu, sv, o);
    if (lane == 0) red[half][w] = sv;
    __syncthreads();
    float inv = 1.f / (red[half][0] + red[half][1] + red[half][2] + red[half][3]);
    if (t < L) attn_sh[half][t] = e * inv;
    else if (t < 104) attn_sh[half][t] = 0.f;
    __syncthreads();

    float4 p4 = make_float4(0.f, 0.f, 0.f, 0.f);
#pragma unroll
    for (int k = 0; k < 13; ++k) {
        float a = attn_sh[half][grp + 8 * k];
        p4.x += a * r[k].x; p4.y += a * r[k].y;
        p4.z += a * r[k].z; p4.w += a * r[k].w;
    }
    p4.x += __shfl_xor_sync(0xffffffffu, p4.x, 16);
    p4.y += __shfl_xor_sync(0xffffffffu, p4.y, 16);
    p4.z += __shfl_xor_sync(0xffffffffu, p4.z, 16);
    p4.w += __shfl_xor_sync(0xffffffffu, p4.w, 16);
    if (lane < 16) *(float4*)&part4[half][w][lane][0] = p4;
    __syncthreads();
    if (t < D) {
        int ci = t >> 2, comp = t & 3;
        float sum = part4[half][0][ci][comp] + part4[half][1][ci][comp]
                  + part4[half][2][ci][comp] + part4[half][3][ci][comp];
        g_weighted[g * D + t] = sum;
    }
}

// ---------------------------------------------------------------------------
// MLP: 128 blocks x 512 threads, 32 rows/block.
// warp wr: kh = wr>>3 (K-half), row tile r0 = (wr&7)*4; lane: c0 = lane*4.
// Inner loop batched by 4 K-iters: 8 independent LDS.128 hoisted ahead of
// 32 fma2 -> deep MLP of shared loads per group.
// ---------------------------------------------------------------------------
template<int K, bool RELU, bool BIAS, bool RESID, bool GSTORE>
__device__ __forceinline__ void gemm_stage(
    const float* __restrict__ xb, const float* __restrict__ ws,
    const float* __restrict__ bias, const float* __restrict__ resid,
    float* __restrict__ obuf, float* __restrict__ part,
    int kh, int r0, int c0, int grow0)
{
    u64 acc[4][2];
#pragma unroll
    for (int i = 0; i < 4; ++i) { acc[i][0] = 0ull; acc[i][1] = 0ull; }

    const int dbase = kh * (K / 2);
#pragma unroll
    for (int i = 0; i < K / 2; i += 4) {
        const int dd = dbase + i;
        // ---- hoisted independent loads: 4x w (LDS.128) + 4x x (LDS.128) ----
        u64 b[4][2];
#pragma unroll
        for (int j = 0; j < 4; ++j) {
            float4 wv = *(const float4*)&ws[(dd + j) * 128 + c0];
            b[j][0] = *(const u64*)&wv.x;
            b[j][1] = *(const u64*)&wv.z;
        }
        float4 xv[4];
#pragma unroll
        for (int row = 0; row < 4; ++row)
            xv[row] = *(const float4*)&xb[(r0 + row) * K + dd];  // broadcast
        // ---- 32 fma2 ----
#pragma unroll
        for (int j = 0; j < 4; ++j) {
#pragma unroll
            for (int row = 0; row < 4; ++row) {
                u64 x = pk2(((const float*)&xv[row])[j]);
                fma2(acc[row][0], x, b[j][0]);
                fma2(acc[row][1], x, b[j][1]);
            }
        }
    }

    if (kh) {
#pragma unroll
        for (int i = 0; i < 4; ++i) {
            float2 a = unpk(acc[i][0]), b2 = unpk(acc[i][1]);
            *(float4*)&part[(r0 + i) * 128 + c0] = make_float4(a.x, a.y, b2.x, b2.y);
        }
    }
    __syncthreads();
    if (!kh) {
        float4 bv = make_float4(0.f, 0.f, 0.f, 0.f);
        if (BIAS) bv = __ldg((const float4*)&bias[c0]);
#pragma unroll
        for (int i = 0; i < 4; ++i) {
            float4 pv = *(const float4*)&part[(r0 + i) * 128 + c0];
            float2 a = unpk(acc[i][0]), b2 = unpk(acc[i][1]);
            float4 o = make_float4(a.x + pv.x + bv.x, a.y + pv.y + bv.y,
                                   b2.x + pv.z + bv.z, b2.y + pv.w + bv.w);
            if (RELU) {
                o.x = fmaxf(o.x, 0.f); o.y = fmaxf(o.y, 0.f);
                o.z = fmaxf(o.z, 0.f); o.w = fmaxf(o.w, 0.f);
            }
            if (RESID) {
                const float* rr = &resid[(r0 + i) * 128 + c0];
                o.x += rr[0]; o.y += rr[1]; o.z += rr[2]; o.w += rr[3];
            }
            if (GSTORE)
                *(float4*)&obuf[(size_t)(grow0 + r0 + i) * 128 + c0] = o;
            else
                *(float4*)&obuf[(r0 + i) * 128 + c0] = o;
        }
    }
    __syncthreads();
}

__global__ __launch_bounds__(512) void mlp_kernel(
    const float* __restrict__ Wq,  const float* __restrict__ Wl0,
    const float* __restrict__ bl0, const float* __restrict__ Wl1,
    const float* __restrict__ bl1, float* __restrict__ out)
{
    extern __shared__ float smem[];
    float* sx   = smem;            // 32x64    =  2048 f
    float* sh0  = smem + 2048;     // 32x128   =  4096 f
    float* sh1  = smem + 6144;     // 32x128   =  4096 f
    float* part = smem + 10240;    // 32x128   =  4096 f
    float* wq   = smem + 14336;    // 64x128   =  8192 f
    float* wl0  = smem + 22528;    // 128x128  = 16384 f
    float* wl1  = smem + 38912;    // 128x128  = 16384 f  (55296 f = 216 KB)

    const int t    = threadIdx.x;
    const int row0 = blockIdx.x * 32;
    const unsigned int sb = (unsigned int)__cvta_generic_to_shared(smem);

    // ---- async staging: G0 = sx + Wq, G1 = Wl0, G2 = Wl1 ----
    {
        const float4* xs = (const float4*)(g_weighted + (size_t)row0 * D);
        cp16(sb + (0 + t * 4) * 4, xs + t);                    // 512 f4
#pragma unroll
        for (int i = 0; i < 4; ++i) {
            int idx = t + i * 512;                             // 2048 f4
            cp16(sb + (14336 + idx * 4) * 4, (const float4*)Wq + idx);
        }
        CP_COMMIT();
#pragma unroll
        for (int i = 0; i < 8; ++i) {
            int idx = t + i * 512;                             // 4096 f4
            cp16(sb + (22528 + idx * 4) * 4, (const float4*)Wl0 + idx);
        }
        CP_COMMIT();
#pragma unroll
        for (int i = 0; i < 8; ++i) {
            int idx = t + i * 512;
            cp16(sb + (38912 + idx * 4) * 4, (const float4*)Wl1 + idx);
        }
        CP_COMMIT();
    }

    const int wr = t >> 5;            // warp 0..15
    const int kh = wr >> 3;           // K-half
    const int r0 = (wr & 7) * 4;      // rows [r0, r0+4)
    const int c0 = (t & 31) * 4;      // cols [c0, c0+4)

    // ---- stage 1: h0 = X @ Wq  (K=64) ----
    CP_WAIT(2);
    __syncthreads();
    gemm_stage<64, false, false, false, false>(sx, wq, nullptr, nullptr,
                                               sh0, part, kh, r0, c0, 0);

    // ---- stage 2: h1 = relu(h0 @ Wl0 + bl0) ----
    CP_WAIT(1);
    __syncthreads();
    gemm_stage<128, true, true, false, false>(sh0, wl0, bl0, nullptr,
                                              sh1, part, kh, r0, c0, 0);

    // ---- stage 3: out = h0 + relu(h1 @ Wl1 + bl1) ----
    CP_WAIT(0);
    __syncthreads();
    gemm_stage<128, true, true, true, true>(sh1, wl1, bl1, sh0,
                                            out, part, kh, r0, c0, row0);
}

// ---------------------------------------------------------------------------
extern "C" void kernel_launch(void* const* d_in, const int* in_sizes, int n_in,
                              void* d_out, int out_size) {
    const float* seqs = (const float*)d_in[0];
    const float* W2   = (const float*)d_in[3];
    const float* p    = (const float*)d_in[6];
    const float* Wq   = (const float*)d_in[7];
    const float* Wl0  = (const float*)d_in[8];
    const float* bl0  = (const float*)d_in[9];
    const float* Wl1  = (const float*)d_in[10];
    const float* bl1  = (const float*)d_in[11];
    float* out = (float*)d_out;

    static bool init_done = false;
    if (!init_done) {
        cudaFuncSetAttribute(mlp_kernel,
                             cudaFuncAttributeMaxDynamicSharedMemorySize, 221184);
        init_done = true;
    }

    attn_kernel<<<NG / 2, 256>>>(seqs, W2, p);
    mlp_kernel<<<NG / 32, 512, 221184>>>(Wq, Wl0, bl0, Wl1, bl1, out);
}